// round 6
// baseline (speedup 1.0000x reference)
#include <cuda_runtime.h>
#include <cuda_bf16.h>
#include <cuda_fp16.h>
#include <float.h>

// Problem constants
#define BB   64
#define DD   64
#define TTm  4096
#define KKm  512
#define TILE 128
#define NTH  128
#define N_ELEM ((size_t)BB * DD * TTm)

// smem byte offsets
#define SM_X2    0         // 128 f
#define SM_C2    512       // 512 f
#define SM_KIDX  2560      // 128 i
#define SM_WRED  3072      // 4 f
#define SM_ZS    3200      // 128x64 f32 [d][t]            (32768 B)
#define SM_AS    35968     // 128 x 72 bf16, stride 144 B  (18432 B)
#define SM_BS    54400     // 128 x 72 bf16, stride 144 B  (18432 B)
#define SM_D     72832     // 128 x 520 fp16, stride 1040 B (133120 B)
#define SM_TOTAL 205952

#define ASTR 144
#define BSTR 144
#define DSTR 1040

__device__ double g_loss;
__device__ float  g_c2[KKm];
__device__ __nv_bfloat16 g_eh[KKm * DD];

// m16n8k16 bf16 MMA, fp32 accumulate in place
__device__ __forceinline__ void mma16816(float* c, const unsigned* a,
                                         unsigned b0, unsigned b1) {
    asm volatile(
        "mma.sync.aligned.m16n8k16.row.col.f32.bf16.bf16.f32 "
        "{%0,%1,%2,%3}, {%4,%5,%6,%7}, {%8,%9}, {%0,%1,%2,%3};"
        : "+f"(c[0]), "+f"(c[1]), "+f"(c[2]), "+f"(c[3])
        : "r"(a[0]), "r"(a[1]), "r"(a[2]), "r"(a[3]), "r"(b0), "r"(b1));
}

// ---------------------------------------------------------------------------
// prep: c2 (rounded squares + pairwise tree, matches reference) + bf16 emb
// ---------------------------------------------------------------------------
__global__ void vq_prep(const float* __restrict__ emb) {
    int k = blockIdx.x * 128 + threadIdx.x;   // 0..511
    if (k == 0) g_loss = 0.0;
    const float* e = emb + k * DD;
    float p[DD];
    #pragma unroll
    for (int d = 0; d < DD; d++) {
        float v = e[d];
        p[d] = __fmul_rn(v, v);
        g_eh[k * DD + d] = __float2bfloat16_rn(v);
    }
    #pragma unroll
    for (int w = DD; w > 1; w >>= 1)
        #pragma unroll
        for (int i = 0; i < DD / 2; i++)
            if (i < w / 2) p[i] = __fadd_rn(p[2 * i], p[2 * i + 1]);
    g_c2[k] = p[0];
}

// exact reference-rounded distance (the bit-exact path that passed round 3)
__device__ __noinline__ float exact_dist(const float* zsp, const float* __restrict__ emb,
                                         int tok, int code, float x2, float c2v) {
    float s = 0.f;
    const float* e = emb + code * DD;
    #pragma unroll
    for (int d = 0; d < DD; d++)
        s = fmaf(zsp[d * TILE + tok], __ldg(e + d), s);
    return __fsub_rn(__fadd_rn(x2, c2v), __fmul_rn(2.f, s));
}

// ---------------------------------------------------------------------------
// main: HMMA bf16 distance GEMM + exact-rescue argmin + fused epilogue
// ---------------------------------------------------------------------------
__global__ __launch_bounds__(NTH, 1)
void vq_main(const float* __restrict__ z, const float* __restrict__ emb,
             float* __restrict__ out) {
    extern __shared__ char smem[];
    const int tid = threadIdx.x;
    const int wid = tid >> 5, lane = tid & 31;
    const int g = lane >> 2, t = lane & 3;
    const int m0 = wid * 32;
    const int tile = blockIdx.x, b = tile >> 5, t0 = (tile & 31) * TILE;
    const size_t zbase = (size_t)b * DD * TTm + t0;

    float* zs   = (float*)(smem + SM_ZS);
    float* x2s  = (float*)(smem + SM_X2);
    float* c2s  = (float*)(smem + SM_C2);
    int*   kidx = (int*)(smem + SM_KIDX);
    float* wred = (float*)(smem + SM_WRED);

    // ---- load z tile fp32 [d][t] coalesced; c2 ----
    for (int i = tid; i < DD * TILE / 4; i += NTH) {
        int row = i >> 5, col = (i & 31) << 2;
        *(float4*)(zs + row * TILE + col) =
            *(const float4*)(z + zbase + (size_t)row * TTm + col);
    }
    for (int i = tid; i < KKm; i += NTH) c2s[i] = g_c2[i];
    __syncthreads();

    // ---- A tile: z -> bf16 [tok][d], padded stride ----
    for (int i = tid; i < TILE * DD / 2; i += NTH) {
        int tok = i >> 5, d = (i & 31) * 2;
        __nv_bfloat16 h0 = __float2bfloat16_rn(zs[d * TILE + tok]);
        __nv_bfloat16 h1 = __float2bfloat16_rn(zs[(d + 1) * TILE + tok]);
        unsigned hp = ((unsigned)__bfloat16_as_ushort(h1) << 16) | __bfloat16_as_ushort(h0);
        *(unsigned*)(smem + SM_AS + tok * ASTR + d * 2) = hp;
    }
    // ---- per-token ||x||^2 (exact fp32 chain) ----
    {
        float s = 0.f;
        #pragma unroll
        for (int d = 0; d < DD; d++) { float v = zs[d * TILE + tid]; s = fmaf(v, v, s); }
        x2s[tid] = s;
    }

    // ---- GEMM: D[128 tok x 512 codes], s = c2 - 2*dot -> fp16 smem ----
    #pragma unroll 1
    for (int bc = 0; bc < 4; bc++) {
        __syncthreads();   // A-convert done (bc=0) / Bs free (bc>0)
        for (int i = tid; i < 128 * 8; i += NTH) {   // load 128-code B chunk
            int code = i >> 3, d8 = (i & 7) << 3;
            *(uint4*)(smem + SM_BS + code * BSTR + d8 * 2) =
                *(const uint4*)(g_eh + (size_t)(bc * 128 + code) * DD + d8);
        }
        __syncthreads();

        #pragma unroll 1
        for (int ns = 0; ns < 4; ns++) {             // 32-code subchunks
            float acc[2][4][4] = {};
            #pragma unroll
            for (int ks = 0; ks < 4; ks++) {
                unsigned a[2][4];
                #pragma unroll
                for (int mt = 0; mt < 2; mt++) {
                    const char* ab = smem + SM_AS + (m0 + mt * 16 + g) * ASTR + ks * 32 + t * 4;
                    a[mt][0] = *(const unsigned*)(ab);
                    a[mt][1] = *(const unsigned*)(ab + 8 * ASTR);
                    a[mt][2] = *(const unsigned*)(ab + 16);
                    a[mt][3] = *(const unsigned*)(ab + 8 * ASTR + 16);
                }
                #pragma unroll
                for (int nt = 0; nt < 4; nt++) {
                    const char* bb = smem + SM_BS + (ns * 32 + nt * 8 + g) * BSTR + ks * 32 + t * 4;
                    unsigned b0 = *(const unsigned*)(bb);
                    unsigned b1 = *(const unsigned*)(bb + 16);
                    mma16816(acc[0][nt], a[0], b0, b1);
                    mma16816(acc[1][nt], a[1], b0, b1);
                }
            }
            // epilogue: s = c2 - 2*dot, store fp16
            #pragma unroll
            for (int nt = 0; nt < 4; nt++) {
                int colg = bc * 128 + ns * 32 + nt * 8 + 2 * t;
                float2 c2v = *(const float2*)(smem + SM_C2 + colg * 4);
                #pragma unroll
                for (int mt = 0; mt < 2; mt++) {
                    int r0 = m0 + mt * 16 + g;
                    __half2 p0 = __floats2half2_rn(fmaf(-2.f, acc[mt][nt][0], c2v.x),
                                                   fmaf(-2.f, acc[mt][nt][1], c2v.y));
                    *(__half2*)(smem + SM_D + r0 * DSTR + colg * 2) = p0;
                    __half2 p1 = __floats2half2_rn(fmaf(-2.f, acc[mt][nt][2], c2v.x),
                                                   fmaf(-2.f, acc[mt][nt][3], c2v.y));
                    *(__half2*)(smem + SM_D + (r0 + 8) * DSTR + colg * 2) = p1;
                }
            }
        }
    }
    __syncthreads();

    // ---- pass 1: approx min over this token's 512 distances ----
    const char* drow = smem + SM_D + tid * DSTR;
    __half2 m2 = __floats2half2_rn(6.0e4f, 6.0e4f);
    #pragma unroll 8
    for (int i = 0; i < 256; i++)
        m2 = __hmin2(m2, *(const __half2*)(drow + i * 4));
    float smin = fminf(__low2float(m2), __high2float(m2));
    const float thresh = smin + 2e-3f;   // ~50 sigma of bf16+fp16 error

    // ---- pass 2: exact rescue on candidates, ascending index tie-break ----
    const float x2 = x2s[tid];
    float bestd = FLT_MAX; int bestk = 0;
    #pragma unroll 4
    for (int i = 0; i < 256; i++) {
        __half2 v = *(const __half2*)(drow + i * 4);
        if (__low2float(v) <= thresh) {
            float ex = exact_dist(zs, emb, tid, 2 * i, x2, c2s[2 * i]);
            if (ex < bestd) { bestd = ex; bestk = 2 * i; }
        }
        if (__high2float(v) <= thresh) {
            float ex = exact_dist(zs, emb, tid, 2 * i + 1, x2, c2s[2 * i + 1]);
            if (ex < bestd) { bestd = ex; bestk = 2 * i + 1; }
        }
    }
    kidx[tid] = bestk;
    __syncthreads();

    // ---- gather + straight-through output + loss (reference rounding) ----
    float lsum = 0.f;
    for (int i = tid; i < DD * TILE; i += NTH) {
        int d = i >> 7, tt = i & 127;
        float q  = __ldg(emb + kidx[tt] * DD + d);
        float zv = zs[d * TILE + tt];
        float diff = __fsub_rn(q, zv);
        out[zbase + (size_t)d * TTm + tt] = __fadd_rn(zv, diff);
        lsum = fmaf(diff, diff, lsum);
    }
    #pragma unroll
    for (int o = 16; o > 0; o >>= 1)
        lsum += __shfl_down_sync(0xffffffffu, lsum, o);
    if (lane == 0) wred[wid] = lsum;
    __syncthreads();
    if (tid == 0)
        atomicAdd(&g_loss, (double)(wred[0] + wred[1] + wred[2] + wred[3]));
}

// ---------------------------------------------------------------------------
__global__ void vq_fin(float* __restrict__ out) {
    double m = g_loss / (double)N_ELEM;
    out[N_ELEM]     = (float)m;
    out[N_ELEM + 1] = (float)(0.25 * m);
}

// ---------------------------------------------------------------------------
extern "C" void kernel_launch(void* const* d_in, const int* in_sizes, int n_in,
                              void* d_out, int out_size) {
    const float* z   = (const float*)d_in[0];
    const float* emb = (const float*)d_in[1];
    float*       out = (float*)d_out;

    (void)cudaFuncSetAttribute(vq_main,
                               cudaFuncAttributeMaxDynamicSharedMemorySize,
                               SM_TOTAL);

    vq_prep<<<4, 128>>>(emb);
    vq_main<<<(BB * TTm) / TILE, NTH, SM_TOTAL>>>(z, emb, out);
    vq_fin<<<1, 1>>>(out);
}